// round 1
// baseline (speedup 1.0000x reference)
#include <cuda_runtime.h>
#include <math.h>

#define N_   4
#define C_   19
#define H_   512
#define W_   1024
#define HW_  (H_ * W_)
#define P_   (N_ * HW_)
#define MIN_KEPT_ 256
#define THRESH_   0.7f
#define IGNORE_   (-1)

// ---- device scratch (no allocations allowed) ----
__device__ double g_sum_wnll;          // sum of w*nll over valid pixels with pred <= 0.7
__device__ double g_sum_w;             // sum of w      over valid pixels with pred <= 0.7
__device__ int    g_cnt_le;            // count of valid pixels with pred <= 0.7
__device__ int    g_num_valid;         // count of valid pixels
__device__ int    g_ov_cnt;            // overflow list length (valid pixels with pred > 0.7)
__device__ int    g_tstride;           // 1 if target is int32, 2 if int64 (read low words)
__device__ float  g_ov_pred[P_];
__device__ float  g_ov_wnll[P_];
__device__ float  g_ov_w[P_];

// ---------------------------------------------------------------------------
// Kernel 0: zero accumulators + detect target element width.
// If target is int64, every odd 32-bit word is the (zero) high half; for int32
// labels in [0,19) the chance 128 consecutive odd words are all zero is ~(1/19)^128.
// ---------------------------------------------------------------------------
__global__ void ohem_init_kernel(const int* __restrict__ tgt32) {
    __shared__ int nz;
    if (threadIdx.x == 0) {
        nz = 0;
        g_sum_wnll = 0.0;
        g_sum_w    = 0.0;
        g_cnt_le    = 0;
        g_num_valid = 0;
        g_ov_cnt    = 0;
    }
    __syncthreads();
    int v = tgt32[2 * threadIdx.x + 1];
    if (v != 0) atomicOr(&nz, 1);
    __syncthreads();
    if (threadIdx.x == 0) g_tstride = nz ? 1 : 2;
}

// ---------------------------------------------------------------------------
// Kernel 1: fused per-pixel log-softmax + gt gather + OHEM-local accumulate.
// One thread per pixel; 19 class loads strided HW_ are fully coalesced per warp.
// ---------------------------------------------------------------------------
__global__ __launch_bounds__(1024)
void ohem_main_kernel(const float* __restrict__ predict,
                      const int*   __restrict__ tgt32,
                      const float* __restrict__ cw) {
    int p = blockIdx.x * blockDim.x + threadIdx.x;   // grid sized exactly to P_
    int stride = g_tstride;

    float wnll = 0.f, wv = 0.f;
    int   cle = 0, cval = 0;

    int label = tgt32[(size_t)p * stride];
    if (label != IGNORE_) {
        cval = 1;
        int n  = p >> 19;              // p / HW_ (HW_ = 2^19)
        int hw = p & (HW_ - 1);
        const float* base = predict + (size_t)n * (C_ * HW_) + hw;

        float x[C_];
#pragma unroll
        for (int c = 0; c < C_; c++) x[c] = base[(size_t)c * HW_];

        float m = x[0];
#pragma unroll
        for (int c = 1; c < C_; c++) m = fmaxf(m, x[c]);

        float s = 0.f;
#pragma unroll
        for (int c = 0; c < C_; c++) s += __expf(x[c] - m);

        float lse = m + __logf(s);
        float lp  = x[label] - lse;     // log p(gt)
        float pr  = __expf(lp);         // p(gt)
        float w   = cw[label];
        float wn  = -lp * w;            // w * nll

        if (pr <= THRESH_) {
            cle = 1; wnll = wn; wv = w;
        } else {
            int i = atomicAdd(&g_ov_cnt, 1);
            g_ov_pred[i] = pr;
            g_ov_wnll[i] = wn;
            g_ov_w[i]    = w;
        }
    }

    // ---- block reduction: 2 floats + 2 ints, then 4 atomics per block ----
#pragma unroll
    for (int o = 16; o > 0; o >>= 1) {
        wnll += __shfl_xor_sync(0xFFFFFFFFu, wnll, o);
        wv   += __shfl_xor_sync(0xFFFFFFFFu, wv,   o);
        cle  += __shfl_xor_sync(0xFFFFFFFFu, cle,  o);
        cval += __shfl_xor_sync(0xFFFFFFFFu, cval, o);
    }
    __shared__ float s_wnll[32], s_wv[32];
    __shared__ int   s_cle[32],  s_cval[32];
    int wid = threadIdx.x >> 5, lid = threadIdx.x & 31;
    if (lid == 0) { s_wnll[wid] = wnll; s_wv[wid] = wv; s_cle[wid] = cle; s_cval[wid] = cval; }
    __syncthreads();
    if (wid == 0) {
        int nw = blockDim.x >> 5;
        wnll = (lid < nw) ? s_wnll[lid] : 0.f;
        wv   = (lid < nw) ? s_wv[lid]   : 0.f;
        cle  = (lid < nw) ? s_cle[lid]  : 0;
        cval = (lid < nw) ? s_cval[lid] : 0;
#pragma unroll
        for (int o = 16; o > 0; o >>= 1) {
            wnll += __shfl_xor_sync(0xFFFFFFFFu, wnll, o);
            wv   += __shfl_xor_sync(0xFFFFFFFFu, wv,   o);
            cle  += __shfl_xor_sync(0xFFFFFFFFu, cle,  o);
            cval += __shfl_xor_sync(0xFFFFFFFFu, cval, o);
        }
        if (lid == 0) {
            atomicAdd(&g_sum_wnll, (double)wnll);
            atomicAdd(&g_sum_w,    (double)wv);
            atomicAdd(&g_cnt_le,    cle);
            atomicAdd(&g_num_valid, cval);
        }
    }
}

// ---------------------------------------------------------------------------
// Kernel 2: finalize. Fast path: count(pred<=0.7) >= MIN_KEPT  =>  thr = 0.7,
// answer already in accumulators. Otherwise do an exact byte-wise radix select
// of the kth-smallest pred over the overflow list and fold in the selected set.
// ---------------------------------------------------------------------------
__global__ __launch_bounds__(1024)
void ohem_fixup_kernel(float* __restrict__ out) {
    __shared__ int      hist[256];
    __shared__ unsigned s_prefix;
    __shared__ int      s_rank;
    __shared__ float    sh_en[32], sh_ew[32];

    int tid = threadIdx.x;
    int c   = g_cnt_le;
    int nv  = g_num_valid;
    int ov  = g_ov_cnt;
    double sn = g_sum_wnll;
    double sw = g_sum_w;

    if (nv > MIN_KEPT_ && c >= MIN_KEPT_) {       // common case: threshold = 0.7
        if (tid == 0) out[0] = (float)(sn / sw);
        return;
    }

    unsigned kbits = 0xFFFFFFFFu;                 // nv <= MIN_KEPT: keep ALL valid
    if (nv > MIN_KEPT_) {
        // Need kth-smallest pred overall; the (255 - c)-th smallest in overflow.
        int rank = MIN_KEPT_ - 1 - c;
        unsigned prefix = 0;
        for (int shift = 24; shift >= 0; shift -= 8) {
            for (int j = tid; j < 256; j += blockDim.x) hist[j] = 0;
            __syncthreads();
            unsigned himask = (shift == 24) ? 0u : (0xFFFFFFFFu << (shift + 8));
            for (int i = tid; i < ov; i += blockDim.x) {
                unsigned b = __float_as_uint(g_ov_pred[i]);
                if ((b & himask) == prefix)
                    atomicAdd(&hist[(b >> shift) & 0xFF], 1);
            }
            __syncthreads();
            if (tid == 0) {
                int acc = 0, j = 0;
                for (; j < 256; j++) {
                    if (acc + hist[j] > rank) break;
                    acc += hist[j];
                }
                s_prefix = prefix | ((unsigned)j << shift);
                s_rank   = rank - acc;
            }
            __syncthreads();
            prefix = s_prefix;
            rank   = s_rank;
            __syncthreads();
        }
        kbits = prefix;   // bits of kth; pred <= kth <=> bits <= kbits (positive floats)
    }

    float en = 0.f, ew = 0.f;
    for (int i = tid; i < ov; i += blockDim.x) {
        unsigned b = __float_as_uint(g_ov_pred[i]);
        if (b <= kbits) { en += g_ov_wnll[i]; ew += g_ov_w[i]; }
    }
#pragma unroll
    for (int o = 16; o > 0; o >>= 1) {
        en += __shfl_xor_sync(0xFFFFFFFFu, en, o);
        ew += __shfl_xor_sync(0xFFFFFFFFu, ew, o);
    }
    int wid = tid >> 5, lid = tid & 31;
    if (lid == 0) { sh_en[wid] = en; sh_ew[wid] = ew; }
    __syncthreads();
    if (wid == 0) {
        int nw = blockDim.x >> 5;
        en = (lid < nw) ? sh_en[lid] : 0.f;
        ew = (lid < nw) ? sh_ew[lid] : 0.f;
#pragma unroll
        for (int o = 16; o > 0; o >>= 1) {
            en += __shfl_xor_sync(0xFFFFFFFFu, en, o);
            ew += __shfl_xor_sync(0xFFFFFFFFu, ew, o);
        }
        if (lid == 0) out[0] = (float)((sn + (double)en) / (sw + (double)ew));
    }
}

// ---------------------------------------------------------------------------
extern "C" void kernel_launch(void* const* d_in, const int* in_sizes, int n_in,
                              void* d_out, int out_size) {
    const float* predict = (const float*)d_in[0];
    const int*   target  = (const int*)d_in[1];   // int32 or int64 — detected on device
    const float* cw      = (const float*)d_in[2];
    float*       out     = (float*)d_out;

    ohem_init_kernel<<<1, 128>>>(target);
    ohem_main_kernel<<<P_ / 1024, 1024>>>(predict, target, cw);
    ohem_fixup_kernel<<<1, 1024>>>(out);
}

// round 2
// speedup vs baseline: 1.3765x; 1.3765x over previous
#include <cuda_runtime.h>
#include <math.h>

#define N_   4
#define C_   19
#define H_   512
#define W_   1024
#define HW_  (H_ * W_)
#define P_   (N_ * HW_)
#define MIN_KEPT_ 256
#define THRESH_   0.7f
#define IGNORE_   (-1)

// ---- device scratch (no allocations allowed) ----
__device__ double g_sum_wnll;          // sum of w*nll over valid pixels with pred <= 0.7
__device__ double g_sum_w;             // sum of w      over valid pixels with pred <= 0.7
__device__ int    g_cnt_le;            // count of valid pixels with pred <= 0.7
__device__ int    g_num_valid;         // count of valid pixels
__device__ int    g_ov_cnt;            // overflow list length (valid pixels with pred > 0.7)
__device__ int    g_tstride;           // 1 if target is int32, 2 if int64 (read low words)
__device__ float  g_ov_pred[P_];
__device__ float  g_ov_wnll[P_];
__device__ float  g_ov_w[P_];

// ---------------------------------------------------------------------------
// Kernel 0: zero accumulators + detect target element width.
// If target is int64, every odd 32-bit word is the (zero) high half; for int32
// labels in [0,19) the chance 128 consecutive odd words are all zero is ~(1/19)^128.
// ---------------------------------------------------------------------------
__global__ void ohem_init_kernel(const int* __restrict__ tgt32) {
    __shared__ int nz;
    if (threadIdx.x == 0) {
        nz = 0;
        g_sum_wnll = 0.0;
        g_sum_w    = 0.0;
        g_cnt_le    = 0;
        g_num_valid = 0;
        g_ov_cnt    = 0;
    }
    __syncthreads();
    int v = tgt32[2 * threadIdx.x + 1];
    if (v != 0) atomicOr(&nz, 1);
    __syncthreads();
    if (threadIdx.x == 0) g_tstride = nz ? 1 : 2;
}

// ---------------------------------------------------------------------------
// Kernel 1: fused per-pixel log-softmax + gt gather + OHEM-local accumulate.
// One thread per pixel; 19 class loads strided HW_ are fully coalesced per warp.
// ---------------------------------------------------------------------------
__global__ __launch_bounds__(1024)
void ohem_main_kernel(const float* __restrict__ predict,
                      const int*   __restrict__ tgt32,
                      const float* __restrict__ cw) {
    int p = blockIdx.x * blockDim.x + threadIdx.x;   // grid sized exactly to P_
    int stride = g_tstride;

    float wnll = 0.f, wv = 0.f;
    int   cle = 0, cval = 0;

    int label = tgt32[(size_t)p * stride];
    if (label != IGNORE_) {
        cval = 1;
        int n  = p >> 19;              // p / HW_ (HW_ = 2^19)
        int hw = p & (HW_ - 1);
        const float* base = predict + (size_t)n * (C_ * HW_) + hw;

        float x[C_];
#pragma unroll
        for (int c = 0; c < C_; c++) x[c] = base[(size_t)c * HW_];

        float m = x[0];
#pragma unroll
        for (int c = 1; c < C_; c++) m = fmaxf(m, x[c]);

        float s = 0.f;
#pragma unroll
        for (int c = 0; c < C_; c++) s += __expf(x[c] - m);

        float lse = m + __logf(s);
        float lp  = x[label] - lse;     // log p(gt)
        float pr  = __expf(lp);         // p(gt)
        float w   = cw[label];
        float wn  = -lp * w;            // w * nll

        if (pr <= THRESH_) {
            cle = 1; wnll = wn; wv = w;
        } else {
            int i = atomicAdd(&g_ov_cnt, 1);
            g_ov_pred[i] = pr;
            g_ov_wnll[i] = wn;
            g_ov_w[i]    = w;
        }
    }

    // ---- block reduction: 2 floats + 2 ints, then 4 atomics per block ----
#pragma unroll
    for (int o = 16; o > 0; o >>= 1) {
        wnll += __shfl_xor_sync(0xFFFFFFFFu, wnll, o);
        wv   += __shfl_xor_sync(0xFFFFFFFFu, wv,   o);
        cle  += __shfl_xor_sync(0xFFFFFFFFu, cle,  o);
        cval += __shfl_xor_sync(0xFFFFFFFFu, cval, o);
    }
    __shared__ float s_wnll[32], s_wv[32];
    __shared__ int   s_cle[32],  s_cval[32];
    int wid = threadIdx.x >> 5, lid = threadIdx.x & 31;
    if (lid == 0) { s_wnll[wid] = wnll; s_wv[wid] = wv; s_cle[wid] = cle; s_cval[wid] = cval; }
    __syncthreads();
    if (wid == 0) {
        int nw = blockDim.x >> 5;
        wnll = (lid < nw) ? s_wnll[lid] : 0.f;
        wv   = (lid < nw) ? s_wv[lid]   : 0.f;
        cle  = (lid < nw) ? s_cle[lid]  : 0;
        cval = (lid < nw) ? s_cval[lid] : 0;
#pragma unroll
        for (int o = 16; o > 0; o >>= 1) {
            wnll += __shfl_xor_sync(0xFFFFFFFFu, wnll, o);
            wv   += __shfl_xor_sync(0xFFFFFFFFu, wv,   o);
            cle  += __shfl_xor_sync(0xFFFFFFFFu, cle,  o);
            cval += __shfl_xor_sync(0xFFFFFFFFu, cval, o);
        }
        if (lid == 0) {
            atomicAdd(&g_sum_wnll, (double)wnll);
            atomicAdd(&g_sum_w,    (double)wv);
            atomicAdd(&g_cnt_le,    cle);
            atomicAdd(&g_num_valid, cval);
        }
    }
}

// ---------------------------------------------------------------------------
// Kernel 2: finalize. Fast path: count(pred<=0.7) >= MIN_KEPT  =>  thr = 0.7,
// answer already in accumulators. Otherwise do an exact byte-wise radix select
// of the kth-smallest pred over the overflow list and fold in the selected set.
// ---------------------------------------------------------------------------
__global__ __launch_bounds__(1024)
void ohem_fixup_kernel(float* __restrict__ out) {
    __shared__ int      hist[256];
    __shared__ unsigned s_prefix;
    __shared__ int      s_rank;
    __shared__ float    sh_en[32], sh_ew[32];

    int tid = threadIdx.x;
    int c   = g_cnt_le;
    int nv  = g_num_valid;
    int ov  = g_ov_cnt;
    double sn = g_sum_wnll;
    double sw = g_sum_w;

    if (nv > MIN_KEPT_ && c >= MIN_KEPT_) {       // common case: threshold = 0.7
        if (tid == 0) out[0] = (float)(sn / sw);
        return;
    }

    unsigned kbits = 0xFFFFFFFFu;                 // nv <= MIN_KEPT: keep ALL valid
    if (nv > MIN_KEPT_) {
        // Need kth-smallest pred overall; the (255 - c)-th smallest in overflow.
        int rank = MIN_KEPT_ - 1 - c;
        unsigned prefix = 0;
        for (int shift = 24; shift >= 0; shift -= 8) {
            for (int j = tid; j < 256; j += blockDim.x) hist[j] = 0;
            __syncthreads();
            unsigned himask = (shift == 24) ? 0u : (0xFFFFFFFFu << (shift + 8));
            for (int i = tid; i < ov; i += blockDim.x) {
                unsigned b = __float_as_uint(g_ov_pred[i]);
                if ((b & himask) == prefix)
                    atomicAdd(&hist[(b >> shift) & 0xFF], 1);
            }
            __syncthreads();
            if (tid == 0) {
                int acc = 0, j = 0;
                for (; j < 256; j++) {
                    if (acc + hist[j] > rank) break;
                    acc += hist[j];
                }
                s_prefix = prefix | ((unsigned)j << shift);
                s_rank   = rank - acc;
            }
            __syncthreads();
            prefix = s_prefix;
            rank   = s_rank;
            __syncthreads();
        }
        kbits = prefix;   // bits of kth; pred <= kth <=> bits <= kbits (positive floats)
    }

    float en = 0.f, ew = 0.f;
    for (int i = tid; i < ov; i += blockDim.x) {
        unsigned b = __float_as_uint(g_ov_pred[i]);
        if (b <= kbits) { en += g_ov_wnll[i]; ew += g_ov_w[i]; }
    }
#pragma unroll
    for (int o = 16; o > 0; o >>= 1) {
        en += __shfl_xor_sync(0xFFFFFFFFu, en, o);
        ew += __shfl_xor_sync(0xFFFFFFFFu, ew, o);
    }
    int wid = tid >> 5, lid = tid & 31;
    if (lid == 0) { sh_en[wid] = en; sh_ew[wid] = ew; }
    __syncthreads();
    if (wid == 0) {
        int nw = blockDim.x >> 5;
        en = (lid < nw) ? sh_en[lid] : 0.f;
        ew = (lid < nw) ? sh_ew[lid] : 0.f;
#pragma unroll
        for (int o = 16; o > 0; o >>= 1) {
            en += __shfl_xor_sync(0xFFFFFFFFu, en, o);
            ew += __shfl_xor_sync(0xFFFFFFFFu, ew, o);
        }
        if (lid == 0) out[0] = (float)((sn + (double)en) / (sw + (double)ew));
    }
}

// ---------------------------------------------------------------------------
extern "C" void kernel_launch(void* const* d_in, const int* in_sizes, int n_in,
                              void* d_out, int out_size) {
    const float* predict = (const float*)d_in[0];
    const int*   target  = (const int*)d_in[1];   // int32 or int64 — detected on device
    const float* cw      = (const float*)d_in[2];
    float*       out     = (float*)d_out;

    ohem_init_kernel<<<1, 128>>>(target);
    ohem_main_kernel<<<P_ / 1024, 1024>>>(predict, target, cw);
    ohem_fixup_kernel<<<1, 1024>>>(out);
}

// round 3
// speedup vs baseline: 1.7154x; 1.2462x over previous
#include <cuda_runtime.h>

#define C_    19
#define HW_   (512*1024)
#define P_    (4*HW_)
#define TPB   256
#define PPT   4                       // pixels per thread (float4)
#define PPB   (TPB*PPT)               // 1024 pixels per block
#define GRID_ (P_/PPB)                // 2048 blocks
#define MIN_KEPT_ 256
#define THRESH_   0.7f

// ---- device scratch (zero-initialized at load; finalize resets after each call) ----
__device__ double g_sum_wnll;
__device__ double g_sum_w;
__device__ int    g_cnt_le;
__device__ int    g_num_valid;
__device__ int    g_ov_cnt;
__device__ int    g_done;
__device__ float  g_ov_pred[P_];
__device__ float  g_ov_wnll[P_];
__device__ float  g_ov_w[P_];

__global__ __launch_bounds__(TPB)
void ohem_fused_kernel(const float* __restrict__ predict,
                       const int*   __restrict__ tgt,     // int32 or int64 (low words)
                       const float* __restrict__ cw,
                       float*       __restrict__ out)
{
    const int tid       = threadIdx.x;
    const int blockBase = blockIdx.x * PPB;
    const int wid = tid >> 5, lid = tid & 31;

    // ---- per-block target dtype detection (in-bounds for both widths) ----
    // Sample odd 32-bit word indices in [blockBase, blockBase+256): for int64 these
    // are high halves of labels (0 or -1); for int32 they are random labels in [0,19).
    __shared__ int s_nz;
    if (tid == 0) s_nz = 0;
    __syncthreads();
    if (tid < 128) {
        int v = tgt[blockBase + 2 * tid + 1];
        if (v != 0 && v != -1) atomicOr(&s_nz, 1);
    }
    __syncthreads();
    const int stride = s_nz ? 1 : 2;

    // ---- fused streaming log-softmax over 4 consecutive pixels ----
    const int p0 = blockBase + tid * PPT;
    const int n  = p0 >> 19;                 // p / HW_
    const int hw = p0 & (HW_ - 1);
    const float4* base =
        reinterpret_cast<const float4*>(predict + (size_t)n * (C_ * HW_) + hw);

    int lab[PPT];
#pragma unroll
    for (int j = 0; j < PPT; j++) lab[j] = tgt[(size_t)(p0 + j) * stride];

    float sum[PPT] = {0.f, 0.f, 0.f, 0.f};
    float xl[PPT]  = {0.f, 0.f, 0.f, 0.f};   // logit of gt class

#pragma unroll
    for (int c = 0; c < C_; c++) {
        float4 v = __ldcs(&base[(size_t)c * (HW_ / 4)]);   // read-once: evict-first
        sum[0] += __expf(v.x); if (lab[0] == c) xl[0] = v.x;
        sum[1] += __expf(v.y); if (lab[1] == c) xl[1] = v.y;
        sum[2] += __expf(v.z); if (lab[2] == c) xl[2] = v.z;
        sum[3] += __expf(v.w); if (lab[3] == c) xl[3] = v.w;
    }

    float wnll = 0.f, wv = 0.f;
    int   cle = 0, cval = 0;
#pragma unroll
    for (int j = 0; j < PPT; j++) {
        if (lab[j] >= 0) {                    // valid (not IGNORE=-1)
            cval++;
            float lse = __logf(sum[j]);
            float nll = lse - xl[j];          // -log p(gt)
            float pr  = __expf(-nll);         // p(gt) = exp(x_gt)/sum
            float w   = cw[lab[j]];
            float wn  = w * nll;
            if (pr <= THRESH_) { cle++; wnll += wn; wv += w; }
            else {
                int i = atomicAdd(&g_ov_cnt, 1);   // rare: pred > 0.7
                g_ov_pred[i] = pr;
                g_ov_wnll[i] = wn;
                g_ov_w[i]    = w;
                __threadfence();
            }
        }
    }

    // ---- block reduction (8 warps) ----
#pragma unroll
    for (int o = 16; o > 0; o >>= 1) {
        wnll += __shfl_xor_sync(0xFFFFFFFFu, wnll, o);
        wv   += __shfl_xor_sync(0xFFFFFFFFu, wv,   o);
        cle  += __shfl_xor_sync(0xFFFFFFFFu, cle,  o);
        cval += __shfl_xor_sync(0xFFFFFFFFu, cval, o);
    }
    __shared__ float s_f0[8], s_f1[8];
    __shared__ int   s_i0[8], s_i1[8];
    if (lid == 0) { s_f0[wid] = wnll; s_f1[wid] = wv; s_i0[wid] = cle; s_i1[wid] = cval; }
    __syncthreads();

    __shared__ int s_last;
    if (wid == 0) {
        wnll = (lid < 8) ? s_f0[lid] : 0.f;
        wv   = (lid < 8) ? s_f1[lid] : 0.f;
        cle  = (lid < 8) ? s_i0[lid] : 0;
        cval = (lid < 8) ? s_i1[lid] : 0;
#pragma unroll
        for (int o = 4; o > 0; o >>= 1) {
            wnll += __shfl_xor_sync(0xFFFFFFFFu, wnll, o);
            wv   += __shfl_xor_sync(0xFFFFFFFFu, wv,   o);
            cle  += __shfl_xor_sync(0xFFFFFFFFu, cle,  o);
            cval += __shfl_xor_sync(0xFFFFFFFFu, cval, o);
        }
        if (lid == 0) {
            atomicAdd(&g_sum_wnll, (double)wnll);
            atomicAdd(&g_sum_w,    (double)wv);
            atomicAdd(&g_cnt_le,    cle);
            atomicAdd(&g_num_valid, cval);
            __threadfence();
            int t = atomicAdd(&g_done, 1);
            s_last = (t == GRID_ - 1);
        }
    }
    __syncthreads();
    if (!s_last) return;

    // ================= last block: finalize =================
    __shared__ double sd_sn, sd_sw;
    __shared__ int    si_c, si_nv, si_ov;
    if (tid == 0) {
        sd_sn = atomicAdd(&g_sum_wnll, 0.0);
        sd_sw = atomicAdd(&g_sum_w,    0.0);
        si_c  = atomicAdd(&g_cnt_le,    0);
        si_nv = atomicAdd(&g_num_valid, 0);
        si_ov = atomicAdd(&g_ov_cnt,    0);
        // reset ALL state for the next graph replay
        g_sum_wnll = 0.0; g_sum_w = 0.0;
        g_cnt_le = 0; g_num_valid = 0; g_ov_cnt = 0; g_done = 0;
    }
    __syncthreads();
    const double sn = sd_sn, sw = sd_sw;
    const int c = si_c, nv = si_nv, ov = si_ov;

    if (nv > MIN_KEPT_ && c >= MIN_KEPT_) {   // common case: threshold = 0.7
        if (tid == 0) out[0] = (float)(sn / sw);
        return;
    }

    // General case: nv <= MIN_KEPT -> keep all valid; else exact radix-select
    // of the kth-smallest pred among the overflow (>0.7) list.
    unsigned kbits = 0xFFFFFFFFu;
    __shared__ int      hist[256];
    __shared__ unsigned s_prefix;
    __shared__ int      s_rank;
    if (nv > MIN_KEPT_) {
        int rank = MIN_KEPT_ - 1 - c;           // 0-indexed rank within overflow
        unsigned prefix = 0;
        for (int shift = 24; shift >= 0; shift -= 8) {
            hist[tid] = 0;                      // TPB == 256
            __syncthreads();
            unsigned himask = (shift == 24) ? 0u : (0xFFFFFFFFu << (shift + 8));
            for (int i = tid; i < ov; i += TPB) {
                unsigned b = __float_as_uint(__ldcg(&g_ov_pred[i]));
                if ((b & himask) == prefix)
                    atomicAdd(&hist[(b >> shift) & 0xFF], 1);
            }
            __syncthreads();
            if (tid == 0) {
                int acc = 0, j = 0;
                for (; j < 256; j++) {
                    if (acc + hist[j] > rank) break;
                    acc += hist[j];
                }
                s_prefix = prefix | ((unsigned)j << shift);
                s_rank   = rank - acc;
            }
            __syncthreads();
            prefix = s_prefix;
            rank   = s_rank;
            __syncthreads();
        }
        kbits = prefix;   // pred <= kth  <=>  bits <= kbits (positive floats)
    }

    float en = 0.f, ew = 0.f;
    for (int i = tid; i < ov; i += TPB) {
        unsigned b = __float_as_uint(__ldcg(&g_ov_pred[i]));
        if (b <= kbits) { en += __ldcg(&g_ov_wnll[i]); ew += __ldcg(&g_ov_w[i]); }
    }
#pragma unroll
    for (int o = 16; o > 0; o >>= 1) {
        en += __shfl_xor_sync(0xFFFFFFFFu, en, o);
        ew += __shfl_xor_sync(0xFFFFFFFFu, ew, o);
    }
    if (lid == 0) { s_f0[wid] = en; s_f1[wid] = ew; }
    __syncthreads();
    if (tid == 0) {
        float ten = 0.f, tew = 0.f;
        for (int k = 0; k < 8; k++) { ten += s_f0[k]; tew += s_f1[k]; }
        out[0] = (float)((sn + (double)ten) / (sw + (double)tew));
    }
}

// ---------------------------------------------------------------------------
extern "C" void kernel_launch(void* const* d_in, const int* in_sizes, int n_in,
                              void* d_out, int out_size) {
    const float* predict = (const float*)d_in[0];
    const int*   target  = (const int*)d_in[1];
    const float* cw      = (const float*)d_in[2];
    float*       out     = (float*)d_out;

    ohem_fused_kernel<<<GRID_, TPB>>>(predict, target, cw, out);
}